// round 4
// baseline (speedup 1.0000x reference)
#include <cuda_runtime.h>
#include <math.h>

#define SEQ 8192
#define EMB 1024
#define MID 1024

#define BM 128
#define BN 128
#define BK 16
#define PAD 4
#define LDA_ (BM + PAD)   // 132 floats: 528B rows, keeps 16B alignment

// ---------------- device scratch (no allocs allowed) ----------------
__device__ float g_Q[(size_t)SEQ * MID];
__device__ float g_K[(size_t)SEQ * MID];
__device__ float g_V[(size_t)SEQ * MID];
__device__ float g_P[(size_t)SEQ * SEQ];      // 256 MB exp-scores
__device__ float g_invq[SEQ];
__device__ float g_invk[SEQ];
__device__ float g_rowsum[SEQ];

// ---------------- GEMM NT: C[M,N] = A[M,K] * B[N,K]^T  (+ epilogue) ----------------
// EPI = 0 : C = dot + bias[n]
// EPI = 1 : C = expf(dot * invm[m] * invn[n])
template <int EPI>
__global__ __launch_bounds__(256, 2)
void gemm_nt(const float* __restrict__ A, const float* __restrict__ B,
             float* __restrict__ C, int M, int N, int K,
             const float* __restrict__ bias,
             const float* __restrict__ invm, const float* __restrict__ invn)
{
    __shared__ float As[2][BK][LDA_];
    __shared__ float Bs[2][BK][LDA_];

    const int tid = threadIdx.x;
    const int tx = tid & 15;       // 0..15 -> 8 cols each
    const int ty = tid >> 4;       // 0..15 -> 8 rows each
    const int m0 = blockIdx.y * BM;
    const int n0 = blockIdx.x * BN;

    // loader: 2048 floats per tile = 512 float4; 256 threads x 2
    const int lrow = tid >> 2;            // 0..63
    const int lk   = (tid & 3) * 4;       // 0,4,8,12

    float acc[8][8];
#pragma unroll
    for (int i = 0; i < 8; i++)
#pragma unroll
        for (int j = 0; j < 8; j++) acc[i][j] = 0.f;

    const int ntiles = K / BK;
    float4 ra[2], rb[2];

    // prologue: load tile 0 -> regs -> buf 0
#pragma unroll
    for (int s = 0; s < 2; s++) {
        int r = lrow + s * 64;
        ra[s] = *(const float4*)&A[(size_t)(m0 + r) * K + lk];
        rb[s] = *(const float4*)&B[(size_t)(n0 + r) * K + lk];
    }
#pragma unroll
    for (int s = 0; s < 2; s++) {
        int r = lrow + s * 64;
        As[0][lk + 0][r] = ra[s].x; As[0][lk + 1][r] = ra[s].y;
        As[0][lk + 2][r] = ra[s].z; As[0][lk + 3][r] = ra[s].w;
        Bs[0][lk + 0][r] = rb[s].x; Bs[0][lk + 1][r] = rb[s].y;
        Bs[0][lk + 2][r] = rb[s].z; Bs[0][lk + 3][r] = rb[s].w;
    }
    __syncthreads();

    for (int t = 0; t < ntiles; t++) {
        const int cur = t & 1;
        const int nxt = cur ^ 1;

        // issue gmem loads for tile t+1 (latency hidden by compute below)
        if (t + 1 < ntiles) {
            int k0 = (t + 1) * BK;
#pragma unroll
            for (int s = 0; s < 2; s++) {
                int r = lrow + s * 64;
                ra[s] = *(const float4*)&A[(size_t)(m0 + r) * K + k0 + lk];
                rb[s] = *(const float4*)&B[(size_t)(n0 + r) * K + k0 + lk];
            }
        }

#pragma unroll
        for (int k = 0; k < BK; k++) {
            float4 a0 = *(const float4*)&As[cur][k][ty * 8];
            float4 a1 = *(const float4*)&As[cur][k][ty * 8 + 4];
            float4 b0 = *(const float4*)&Bs[cur][k][tx * 8];
            float4 b1 = *(const float4*)&Bs[cur][k][tx * 8 + 4];
            float a[8] = {a0.x, a0.y, a0.z, a0.w, a1.x, a1.y, a1.z, a1.w};
            float b[8] = {b0.x, b0.y, b0.z, b0.w, b1.x, b1.y, b1.z, b1.w};
#pragma unroll
            for (int i = 0; i < 8; i++)
#pragma unroll
                for (int j = 0; j < 8; j++) acc[i][j] += a[i] * b[j];
        }

        // commit tile t+1 into the other buffer
        if (t + 1 < ntiles) {
#pragma unroll
            for (int s = 0; s < 2; s++) {
                int r = lrow + s * 64;
                As[nxt][lk + 0][r] = ra[s].x; As[nxt][lk + 1][r] = ra[s].y;
                As[nxt][lk + 2][r] = ra[s].z; As[nxt][lk + 3][r] = ra[s].w;
                Bs[nxt][lk + 0][r] = rb[s].x; Bs[nxt][lk + 1][r] = rb[s].y;
                Bs[nxt][lk + 2][r] = rb[s].z; Bs[nxt][lk + 3][r] = rb[s].w;
            }
        }
        __syncthreads();
    }

    if (EPI == 0) {
        float bv[8];
#pragma unroll
        for (int j = 0; j < 8; j++) bv[j] = bias[n0 + tx * 8 + j];
#pragma unroll
        for (int i = 0; i < 8; i++) {
            int row = m0 + ty * 8 + i;
            float* cp = C + (size_t)row * N + n0 + tx * 8;
            float4 o0, o1;
            o0.x = acc[i][0] + bv[0]; o0.y = acc[i][1] + bv[1];
            o0.z = acc[i][2] + bv[2]; o0.w = acc[i][3] + bv[3];
            o1.x = acc[i][4] + bv[4]; o1.y = acc[i][5] + bv[5];
            o1.z = acc[i][6] + bv[6]; o1.w = acc[i][7] + bv[7];
            *(float4*)cp = o0;
            *(float4*)(cp + 4) = o1;
        }
    } else {
        float ik[8];
#pragma unroll
        for (int j = 0; j < 8; j++) ik[j] = invn[n0 + tx * 8 + j];
#pragma unroll
        for (int i = 0; i < 8; i++) {
            int row = m0 + ty * 8 + i;
            float iq = invm[row];
            float* cp = C + (size_t)row * N + n0 + tx * 8;
            float4 o0, o1;
            o0.x = __expf(acc[i][0] * iq * ik[0]);
            o0.y = __expf(acc[i][1] * iq * ik[1]);
            o0.z = __expf(acc[i][2] * iq * ik[2]);
            o0.w = __expf(acc[i][3] * iq * ik[3]);
            o1.x = __expf(acc[i][4] * iq * ik[4]);
            o1.y = __expf(acc[i][5] * iq * ik[5]);
            o1.z = __expf(acc[i][6] * iq * ik[6]);
            o1.w = __expf(acc[i][7] * iq * ik[7]);
            *(float4*)cp = o0;
            *(float4*)(cp + 4) = o1;
        }
    }
}

// ---------------- GEMM NN: C[M,N] = A[M,K] * B[K,N], epilogue C *= 1/rowsum[m] ----
__global__ __launch_bounds__(256, 2)
void gemm_nn_scale(const float* __restrict__ A, const float* __restrict__ B,
                   float* __restrict__ C, int M, int N, int K,
                   const float* __restrict__ rowsum)
{
    __shared__ float As[2][BK][LDA_];
    __shared__ float Bs[2][BK][LDA_];

    const int tid = threadIdx.x;
    const int tx = tid & 15;
    const int ty = tid >> 4;
    const int m0 = blockIdx.y * BM;
    const int n0 = blockIdx.x * BN;

    const int lrow = tid >> 2;          // A loader: 0..63
    const int lk   = (tid & 3) * 4;

    const int bkr = tid >> 4;           // B loader row: 0..15
    const int bc  = (tid & 15) * 4;     // 0..60

    float acc[8][8];
#pragma unroll
    for (int i = 0; i < 8; i++)
#pragma unroll
        for (int j = 0; j < 8; j++) acc[i][j] = 0.f;

    const int ntiles = K / BK;
    float4 ra[2], rb0, rb1;

    // prologue: tile 0 -> buf 0
#pragma unroll
    for (int s = 0; s < 2; s++) {
        int r = lrow + s * 64;
        ra[s] = *(const float4*)&A[(size_t)(m0 + r) * K + lk];
    }
    {
        const float* bp = &B[(size_t)bkr * N + n0 + bc];
        rb0 = *(const float4*)bp;
        rb1 = *(const float4*)(bp + 64);
    }
#pragma unroll
    for (int s = 0; s < 2; s++) {
        int r = lrow + s * 64;
        As[0][lk + 0][r] = ra[s].x; As[0][lk + 1][r] = ra[s].y;
        As[0][lk + 2][r] = ra[s].z; As[0][lk + 3][r] = ra[s].w;
    }
    *(float4*)&Bs[0][bkr][bc] = rb0;
    *(float4*)&Bs[0][bkr][bc + 64] = rb1;
    __syncthreads();

    for (int t = 0; t < ntiles; t++) {
        const int cur = t & 1;
        const int nxt = cur ^ 1;

        if (t + 1 < ntiles) {
            int k0 = (t + 1) * BK;
#pragma unroll
            for (int s = 0; s < 2; s++) {
                int r = lrow + s * 64;
                ra[s] = *(const float4*)&A[(size_t)(m0 + r) * K + k0 + lk];
            }
            const float* bp = &B[(size_t)(k0 + bkr) * N + n0 + bc];
            rb0 = *(const float4*)bp;
            rb1 = *(const float4*)(bp + 64);
        }

#pragma unroll
        for (int k = 0; k < BK; k++) {
            float4 a0 = *(const float4*)&As[cur][k][ty * 8];
            float4 a1 = *(const float4*)&As[cur][k][ty * 8 + 4];
            float4 b0 = *(const float4*)&Bs[cur][k][tx * 8];
            float4 b1 = *(const float4*)&Bs[cur][k][tx * 8 + 4];
            float a[8] = {a0.x, a0.y, a0.z, a0.w, a1.x, a1.y, a1.z, a1.w};
            float b[8] = {b0.x, b0.y, b0.z, b0.w, b1.x, b1.y, b1.z, b1.w};
#pragma unroll
            for (int i = 0; i < 8; i++)
#pragma unroll
                for (int j = 0; j < 8; j++) acc[i][j] += a[i] * b[j];
        }

        if (t + 1 < ntiles) {
#pragma unroll
            for (int s = 0; s < 2; s++) {
                int r = lrow + s * 64;
                As[nxt][lk + 0][r] = ra[s].x; As[nxt][lk + 1][r] = ra[s].y;
                As[nxt][lk + 2][r] = ra[s].z; As[nxt][lk + 3][r] = ra[s].w;
            }
            *(float4*)&Bs[nxt][bkr][bc] = rb0;
            *(float4*)&Bs[nxt][bkr][bc + 64] = rb1;
        }
        __syncthreads();
    }

#pragma unroll
    for (int i = 0; i < 8; i++) {
        int row = m0 + ty * 8 + i;
        float s = 1.0f / rowsum[row];
        float* cp = C + (size_t)row * N + n0 + tx * 8;
        float4 o0, o1;
        o0.x = acc[i][0] * s; o0.y = acc[i][1] * s;
        o0.z = acc[i][2] * s; o0.w = acc[i][3] * s;
        o1.x = acc[i][4] * s; o1.y = acc[i][5] * s;
        o1.z = acc[i][6] * s; o1.w = acc[i][7] * s;
        *(float4*)cp = o0;
        *(float4*)(cp + 4) = o1;
    }
}

// ---------------- per-row rsqrt(sum of squares) ----------------
__global__ void rownorm_kernel(const float* __restrict__ X, float* __restrict__ out, int cols)
{
    int row = blockIdx.x;
    const float4* p = (const float4*)(X + (size_t)row * cols);
    float s = 0.f;
    for (int i = threadIdx.x; i < cols / 4; i += blockDim.x) {
        float4 v = p[i];
        s += v.x * v.x + v.y * v.y + v.z * v.z + v.w * v.w;
    }
    __shared__ float red[256];
    red[threadIdx.x] = s;
    __syncthreads();
    for (int off = 128; off > 0; off >>= 1) {
        if (threadIdx.x < off) red[threadIdx.x] += red[threadIdx.x + off];
        __syncthreads();
    }
    if (threadIdx.x == 0) out[row] = rsqrtf(red[0]);
}

// ---------------- per-row sum over P ----------------
__global__ void rowsum_kernel(const float* __restrict__ P, float* __restrict__ out)
{
    int row = blockIdx.x;
    const float4* p = (const float4*)(P + (size_t)row * SEQ);
    float s = 0.f;
    for (int i = threadIdx.x; i < SEQ / 4; i += blockDim.x) {
        float4 v = p[i];
        s += v.x + v.y + v.z + v.w;
    }
    __shared__ float red[256];
    red[threadIdx.x] = s;
    __syncthreads();
    for (int off = 128; off > 0; off >>= 1) {
        if (threadIdx.x < off) red[threadIdx.x] += red[threadIdx.x + off];
        __syncthreads();
    }
    if (threadIdx.x == 0) out[row] = red[0];
}

// ---------------- host ----------------
extern "C" void kernel_launch(void* const* d_in, const int* in_sizes, int n_in,
                              void* d_out, int out_size)
{
    const float* X  = (const float*)d_in[0];
    const float* Wq = (const float*)d_in[1];
    const float* bq = (const float*)d_in[2];
    const float* Wk = (const float*)d_in[3];
    const float* bk = (const float*)d_in[4];
    const float* Wv = (const float*)d_in[5];
    const float* bv = (const float*)d_in[6];
    float* out = (float*)d_out;

    float *Q, *Kp, *V, *P, *invq, *invk, *rowsum;
    cudaGetSymbolAddress((void**)&Q,      g_Q);
    cudaGetSymbolAddress((void**)&Kp,     g_K);
    cudaGetSymbolAddress((void**)&V,      g_V);
    cudaGetSymbolAddress((void**)&P,      g_P);
    cudaGetSymbolAddress((void**)&invq,   g_invq);
    cudaGetSymbolAddress((void**)&invk,   g_invk);
    cudaGetSymbolAddress((void**)&rowsum, g_rowsum);

    dim3 blk(256);

    // 1) QKV projections (NT + bias)
    dim3 gproj(MID / BN, SEQ / BM);
    gemm_nt<0><<<gproj, blk>>>(X, Wq, Q,  SEQ, MID, EMB, bq, nullptr, nullptr);
    gemm_nt<0><<<gproj, blk>>>(X, Wk, Kp, SEQ, MID, EMB, bk, nullptr, nullptr);
    gemm_nt<0><<<gproj, blk>>>(X, Wv, V,  SEQ, MID, EMB, bv, nullptr, nullptr);

    // 2) inverse row norms
    rownorm_kernel<<<SEQ, 256>>>(Q,  invq, MID);
    rownorm_kernel<<<SEQ, 256>>>(Kp, invk, MID);

    // 3) P = exp(QK^T * invq x invk)   (scores bounded in [-1,1]: no max needed)
    dim3 gsc(SEQ / BN, SEQ / BM);
    gemm_nt<1><<<gsc, blk>>>(Q, Kp, P, SEQ, SEQ, MID, nullptr, invq, invk);

    // 4) softmax denominators
    rowsum_kernel<<<SEQ, 256>>>(P, rowsum);

    // 5) out = (P @ V) / rowsum
    dim3 gout(MID / BN, SEQ / BM);
    gemm_nn_scale<<<gout, blk>>>(P, V, out, SEQ, MID, SEQ, rowsum);
}

// round 16
// speedup vs baseline: 2.2391x; 2.2391x over previous
#include <cuda_runtime.h>
#include <cuda_bf16.h>
#include <math.h>
#include <stdint.h>

#define SEQ 8192
#define EMB 1024
#define MID 1024
#define K3P  (3*EMB)    // 3072  : packed K for projections & scores
#define K3PV (3*SEQ)    // 24576 : packed K for PV

#define BM 128
#define BN 128
#define SROW  72                    // bf16 per smem row (64 data + 8 pad)
#define SROWB 144                   // bytes per smem row
#define TILE_BYTES (128 * SROWB)    // 18432
#define TCG_SMEM_BYTES (4 * TILE_BYTES)   // 73728: A0,B0,A1,B1

// ---------------- device scratch (no allocs allowed) ----------------
__device__ __nv_bfloat16 g_Xcat [(size_t)SEQ*K3P];
__device__ __nv_bfloat16 g_Wqcat[(size_t)MID*K3P];
__device__ __nv_bfloat16 g_Wkcat[(size_t)MID*K3P];
__device__ __nv_bfloat16 g_Wvcat[(size_t)MID*K3P];
__device__ __nv_bfloat16 g_Qcat [(size_t)SEQ*K3P];
__device__ __nv_bfloat16 g_Kcat [(size_t)SEQ*K3P];
__device__ float         g_V    [(size_t)SEQ*MID];
__device__ __nv_bfloat16 g_VtCat[(size_t)MID*K3PV];
__device__ __nv_bfloat16 g_Pcat [(size_t)SEQ*K3PV];   // 384 MB
__device__ float g_invq[SEQ];
__device__ float g_invk[SEQ];
__device__ float g_rowsum[SEQ];

// ---------------- PTX helpers (baseline compute_103-safe) ----------------
__device__ __forceinline__ uint32_t smem_u32(const void* p) {
    uint32_t a;
    asm("{ .reg .u64 t; cvta.to.shared.u64 t, %1; cvt.u32.u64 %0, t; }" : "=r"(a) : "l"(p));
    return a;
}
__device__ __forceinline__ void cp16(uint32_t saddr, const void* g) {
    asm volatile("cp.async.cg.shared.global [%0], [%1], 16;" :: "r"(saddr), "l"(g));
}
__device__ __forceinline__ void ldsm_x4(uint32_t* r, uint32_t addr) {
    asm volatile("ldmatrix.sync.aligned.m8n8.x4.shared.b16 {%0,%1,%2,%3}, [%4];"
                 : "=r"(r[0]), "=r"(r[1]), "=r"(r[2]), "=r"(r[3]) : "r"(addr));
}
__device__ __forceinline__ void mma16816(float* c, const uint32_t* a, uint32_t b0, uint32_t b1) {
    asm volatile(
        "mma.sync.aligned.m16n8k16.row.col.f32.bf16.bf16.f32 "
        "{%0,%1,%2,%3}, {%4,%5,%6,%7}, {%8,%9}, {%0,%1,%2,%3};"
        : "+f"(c[0]), "+f"(c[1]), "+f"(c[2]), "+f"(c[3])
        : "r"(a[0]), "r"(a[1]), "r"(a[2]), "r"(a[3]), "r"(b0), "r"(b1));
}

__device__ __forceinline__ void issue_chunk(const __nv_bfloat16* Ap, const __nv_bfloat16* Bp,
                                            uint32_t abuf, uint32_t bbuf, int K3, int tid)
{
#pragma unroll
    for (int i = 0; i < 4; i++) {
        int idx = tid + i * 256;          // 0..1023: 128 rows x 8 x 16B
        int row = idx >> 3, v = idx & 7;
        cp16(abuf + row * SROWB + v * 16, Ap + (size_t)row * K3 + v * 8);
        cp16(bbuf + row * SROWB + v * 16, Bp + (size_t)row * K3 + v * 8);
    }
    asm volatile("cp.async.commit_group;" ::: "memory");
}

// hi/lo split-cat store of a bf16x2 pair
__device__ __forceinline__ void store_cat(__nv_bfloat16* out, int ncat, int row, int col,
                                          float y0, float y1, bool bside)
{
    __nv_bfloat16 h0 = __float2bfloat16(y0), h1 = __float2bfloat16(y1);
    __nv_bfloat16 l0 = __float2bfloat16(y0 - __bfloat162float(h0));
    __nv_bfloat16 l1 = __float2bfloat16(y1 - __bfloat162float(h1));
    __nv_bfloat162 hv; hv.x = h0; hv.y = h1;
    __nv_bfloat162 lv; lv.x = l0; lv.y = l1;
    __nv_bfloat16* base = out + (size_t)row * (3 * (size_t)ncat) + col;
    *(__nv_bfloat162*)(base) = hv;
    if (bside) { *(__nv_bfloat162*)(base + ncat) = hv; *(__nv_bfloat162*)(base + 2*(size_t)ncat) = lv; }
    else       { *(__nv_bfloat162*)(base + ncat) = lv; *(__nv_bfloat162*)(base + 2*(size_t)ncat) = hv; }
}

// ---------------- warp-MMA NT GEMM: C[M,N] = A[M,K3] * B[N,K3]^T ----------------
// EPI 0: y=acc+bias[n] -> A-side cat [hi|lo|hi]      (Q)
// EPI 1: y=acc+bias[n] -> B-side cat [hi|hi|lo]      (K)
// EPI 2: y=acc+bias[n] -> fp32                       (V)
// EPI 3: y=expf(acc*invm[m]*invn[n]) -> A-side cat   (P)
// EPI 4: y=acc/rowsum[m] -> fp32                     (out)
template <int EPI>
__global__ __launch_bounds__(256)
void tc_gemm(const __nv_bfloat16* __restrict__ A, const __nv_bfloat16* __restrict__ B,
             int M, int N, int K3,
             float* __restrict__ outf, __nv_bfloat16* __restrict__ outcat, int ncat,
             const float* __restrict__ bias, const float* __restrict__ invm,
             const float* __restrict__ invn, const float* __restrict__ rowsum)
{
    extern __shared__ char smem[];
    const uint32_t sbase = smem_u32(smem);
    const int tid  = threadIdx.x;
    const int lane = tid & 31, wid = tid >> 5;
    const int wm = wid & 3;         // 4 warps over M (32 rows each)
    const int wn = wid >> 2;        // 2 warps over N (64 cols each)
    const int m0 = blockIdx.y * BM;
    const int n0 = blockIdx.x * BN;

    float acc[2][8][4];
#pragma unroll
    for (int i = 0; i < 2; i++)
#pragma unroll
        for (int j = 0; j < 8; j++)
#pragma unroll
            for (int q = 0; q < 4; q++) acc[i][j][q] = 0.f;

    const int NCH = K3 >> 6;

    // prologue: chunk 0 -> buffer 0
    issue_chunk(A + (size_t)m0 * K3, B + (size_t)n0 * K3,
                sbase, sbase + TILE_BYTES, K3, tid);

    for (int t = 0; t < NCH; t++) {
        if (t + 1 < NCH) {
            int b = (t + 1) & 1;
            issue_chunk(A + (size_t)m0 * K3 + (t + 1) * 64,
                        B + (size_t)n0 * K3 + (t + 1) * 64,
                        sbase + (b * 2) * TILE_BYTES,
                        sbase + (b * 2 + 1) * TILE_BYTES, K3, tid);
            asm volatile("cp.async.wait_group 1;" ::: "memory");
        } else {
            asm volatile("cp.async.wait_group 0;" ::: "memory");
        }
        __syncthreads();

        const uint32_t abuf = sbase + ((t & 1) * 2) * TILE_BYTES;
        const uint32_t bbuf = abuf + TILE_BYTES;
        const uint32_t lrow = (lane & 15);
        const uint32_t lhalf = (lane >> 4) * 16;

#pragma unroll
        for (int kk = 0; kk < 4; kk++) {
            uint32_t af[2][4];
#pragma unroll
            for (int tm = 0; tm < 2; tm++)
                ldsm_x4(af[tm], abuf + (wm * 32 + tm * 16 + lrow) * SROWB + kk * 32 + lhalf);
            uint32_t bf[4][4];
#pragma unroll
            for (int g = 0; g < 4; g++)
                ldsm_x4(bf[g], bbuf + (wn * 64 + g * 16 + lrow) * SROWB + kk * 32 + lhalf);
#pragma unroll
            for (int tm = 0; tm < 2; tm++)
#pragma unroll
                for (int g = 0; g < 4; g++) {
                    mma16816(acc[tm][2 * g + 0], af[tm], bf[g][0], bf[g][2]);
                    mma16816(acc[tm][2 * g + 1], af[tm], bf[g][1], bf[g][3]);
                }
        }
        __syncthreads();
    }

    // ---------------- epilogue (fragment layout: r=lane>>2 (+8), c=2*(lane&3)) ----
    const int r_base = m0 + wm * 32;
    const int c_base = n0 + wn * 64;
#pragma unroll
    for (int tm = 0; tm < 2; tm++) {
        const int r0 = r_base + tm * 16 + (lane >> 2);
        const int r1 = r0 + 8;
        float sm0 = 0.f, sm1 = 0.f;
        if (EPI == 3) { sm0 = invm[r0]; sm1 = invm[r1]; }
        if (EPI == 4) { sm0 = 1.0f / rowsum[r0]; sm1 = 1.0f / rowsum[r1]; }
#pragma unroll
        for (int tn = 0; tn < 8; tn++) {
            const int c = c_base + tn * 8 + (lane & 3) * 2;
            float y00 = acc[tm][tn][0], y01 = acc[tm][tn][1];
            float y10 = acc[tm][tn][2], y11 = acc[tm][tn][3];
            if (EPI == 0 || EPI == 1 || EPI == 2) {
                float b0 = bias[c], b1 = bias[c + 1];
                y00 += b0; y01 += b1; y10 += b0; y11 += b1;
            }
            if (EPI == 3) {
                float i0 = invn[c], i1 = invn[c + 1];
                y00 = __expf(y00 * sm0 * i0); y01 = __expf(y01 * sm0 * i1);
                y10 = __expf(y10 * sm1 * i0); y11 = __expf(y11 * sm1 * i1);
            }
            if (EPI == 4) { y00 *= sm0; y01 *= sm0; y10 *= sm1; y11 *= sm1; }

            if (EPI == 2 || EPI == 4) {
                float2 v0 = make_float2(y00, y01);
                float2 v1 = make_float2(y10, y11);
                *(float2*)(outf + (size_t)r0 * N + c) = v0;
                *(float2*)(outf + (size_t)r1 * N + c) = v1;
            } else {
                store_cat(outcat, ncat, r0, c, y00, y01, EPI == 1);
                store_cat(outcat, ncat, r1, c, y10, y11, EPI == 1);
            }
        }
    }
}

// ---------------- pack fp32 -> bf16 split-cat ----------------
// aside=1: [hi|lo|hi] ; aside=0: [hi|hi|lo]
__global__ void pack_split(const float* __restrict__ in, __nv_bfloat16* __restrict__ out,
                           int R, int C, int aside)
{
    int c4n = C >> 2;
    int i = blockIdx.x * 256 + threadIdx.x;
    if (i >= R * c4n) return;
    int r = i / c4n;
    int c = (i - r * c4n) * 4;
    float4 v = *(const float4*)(in + (size_t)r * C + c);
    __nv_bfloat16 h0 = __float2bfloat16(v.x), h1 = __float2bfloat16(v.y);
    __nv_bfloat16 h2 = __float2bfloat16(v.z), h3 = __float2bfloat16(v.w);
    __nv_bfloat16 l0 = __float2bfloat16(v.x - __bfloat162float(h0));
    __nv_bfloat16 l1 = __float2bfloat16(v.y - __bfloat162float(h1));
    __nv_bfloat16 l2 = __float2bfloat16(v.z - __bfloat162float(h2));
    __nv_bfloat16 l3 = __float2bfloat16(v.w - __bfloat162float(h3));
    __nv_bfloat162 hA, hB, lA, lB;
    hA.x = h0; hA.y = h1; hB.x = h2; hB.y = h3;
    lA.x = l0; lA.y = l1; lB.x = l2; lB.y = l3;
    __nv_bfloat16* b = out + (size_t)r * 3 * C + c;
    *(__nv_bfloat162*)(b) = hA; *(__nv_bfloat162*)(b + 2) = hB;
    if (aside) {
        *(__nv_bfloat162*)(b + C) = lA;     *(__nv_bfloat162*)(b + C + 2) = lB;
        *(__nv_bfloat162*)(b + 2*C) = hA;   *(__nv_bfloat162*)(b + 2*C + 2) = hB;
    } else {
        *(__nv_bfloat162*)(b + C) = hA;     *(__nv_bfloat162*)(b + C + 2) = hB;
        *(__nv_bfloat162*)(b + 2*C) = lA;   *(__nv_bfloat162*)(b + 2*C + 2) = lB;
    }
}

// ---------------- V [SEQ x MID] fp32 -> VtCat [MID x 3*SEQ] (B-side) ----------------
__global__ void transpose_split_v(const float* __restrict__ V, __nv_bfloat16* __restrict__ VtCat)
{
    __shared__ float tile[32][33];
    const int n0 = blockIdx.x * 32;   // MID dim
    const int s0 = blockIdx.y * 32;   // SEQ dim
    for (int i = threadIdx.y; i < 32; i += 8)
        tile[i][threadIdx.x] = V[(size_t)(s0 + i) * MID + n0 + threadIdx.x];
    __syncthreads();
    for (int i = threadIdx.y; i < 32; i += 8) {
        int n = n0 + i;
        int sv = s0 + threadIdx.x;
        float y = tile[threadIdx.x][i];
        __nv_bfloat16 h = __float2bfloat16(y);
        __nv_bfloat16 l = __float2bfloat16(y - __bfloat162float(h));
        __nv_bfloat16* b = VtCat + (size_t)n * K3PV;
        b[sv] = h; b[SEQ + sv] = h; b[2 * SEQ + sv] = l;
    }
}

// ---------------- per-row rsqrt(sum sq) over cat (hi+lo) ----------------
__global__ void rownorm_cat(const __nv_bfloat16* __restrict__ cat, int C,
                            int hib, int lob, float* __restrict__ out)
{
    int row = blockIdx.x;
    const __nv_bfloat16* h = cat + (size_t)row * 3 * C + (size_t)hib * C;
    const __nv_bfloat16* l = cat + (size_t)row * 3 * C + (size_t)lob * C;
    float ssum = 0.f;
    for (int c = threadIdx.x; c < C; c += blockDim.x) {
        float y = __bfloat162float(h[c]) + __bfloat162float(l[c]);
        ssum += y * y;
    }
    __shared__ float red[256];
    red[threadIdx.x] = ssum;
    __syncthreads();
    for (int off = 128; off > 0; off >>= 1) {
        if (threadIdx.x < off) red[threadIdx.x] += red[threadIdx.x + off];
        __syncthreads();
    }
    if (threadIdx.x == 0) out[row] = rsqrtf(red[0]);
}

// ---------------- per-row sum over Pcat (hi+lo) ----------------
__global__ void rowsum_cat(const __nv_bfloat16* __restrict__ cat, float* __restrict__ out)
{
    int row = blockIdx.x;
    const __nv_bfloat16* h = cat + (size_t)row * K3PV;
    const __nv_bfloat16* l = h + SEQ;
    float ssum = 0.f;
    for (int c = threadIdx.x; c < SEQ; c += blockDim.x)
        ssum += __bfloat162float(h[c]) + __bfloat162float(l[c]);
    __shared__ float red[256];
    red[threadIdx.x] = ssum;
    __syncthreads();
    for (int off = 128; off > 0; off >>= 1) {
        if (threadIdx.x < off) red[threadIdx.x] += red[threadIdx.x + off];
        __syncthreads();
    }
    if (threadIdx.x == 0) out[row] = red[0];
}

// ---------------- host ----------------
extern "C" void kernel_launch(void* const* d_in, const int* in_sizes, int n_in,
                              void* d_out, int out_size)
{
    const float* X  = (const float*)d_in[0];
    const float* Wq = (const float*)d_in[1];
    const float* bq = (const float*)d_in[2];
    const float* Wk = (const float*)d_in[3];
    const float* bk = (const float*)d_in[4];
    const float* Wv = (const float*)d_in[5];
    const float* bv = (const float*)d_in[6];
    float* out = (float*)d_out;

    __nv_bfloat16 *Xcat, *Wqcat, *Wkcat, *Wvcat, *Qcat, *Kcat, *VtCat, *Pcat;
    float *V, *invq, *invk, *rowsum;
    cudaGetSymbolAddress((void**)&Xcat,  g_Xcat);
    cudaGetSymbolAddress((void**)&Wqcat, g_Wqcat);
    cudaGetSymbolAddress((void**)&Wkcat, g_Wkcat);
    cudaGetSymbolAddress((void**)&Wvcat, g_Wvcat);
    cudaGetSymbolAddress((void**)&Qcat,  g_Qcat);
    cudaGetSymbolAddress((void**)&Kcat,  g_Kcat);
    cudaGetSymbolAddress((void**)&V,     g_V);
    cudaGetSymbolAddress((void**)&VtCat, g_VtCat);
    cudaGetSymbolAddress((void**)&Pcat,  g_Pcat);
    cudaGetSymbolAddress((void**)&invq,  g_invq);
    cudaGetSymbolAddress((void**)&invk,  g_invk);
    cudaGetSymbolAddress((void**)&rowsum, g_rowsum);

    cudaFuncSetAttribute(tc_gemm<0>, cudaFuncAttributeMaxDynamicSharedMemorySize, TCG_SMEM_BYTES);
    cudaFuncSetAttribute(tc_gemm<1>, cudaFuncAttributeMaxDynamicSharedMemorySize, TCG_SMEM_BYTES);
    cudaFuncSetAttribute(tc_gemm<2>, cudaFuncAttributeMaxDynamicSharedMemorySize, TCG_SMEM_BYTES);
    cudaFuncSetAttribute(tc_gemm<3>, cudaFuncAttributeMaxDynamicSharedMemorySize, TCG_SMEM_BYTES);
    cudaFuncSetAttribute(tc_gemm<4>, cudaFuncAttributeMaxDynamicSharedMemorySize, TCG_SMEM_BYTES);

    // 1) pack inputs to bf16 split-cat
    {
        int nblk = (SEQ * (EMB / 4) + 255) / 256;
        pack_split<<<nblk, 256>>>(X, Xcat, SEQ, EMB, 1);          // A-side
        int wblk = (MID * (EMB / 4) + 255) / 256;
        pack_split<<<wblk, 256>>>(Wq, Wqcat, MID, EMB, 0);        // B-side
        pack_split<<<wblk, 256>>>(Wk, Wkcat, MID, EMB, 0);
        pack_split<<<wblk, 256>>>(Wv, Wvcat, MID, EMB, 0);
    }

    dim3 blk(256);
    // 2) projections: Q (A-side cat), K (B-side cat), V (fp32)
    dim3 gproj(MID / BN, SEQ / BM);
    tc_gemm<0><<<gproj, blk, TCG_SMEM_BYTES>>>(Xcat, Wqcat, SEQ, MID, K3P,
        nullptr, Qcat, MID, bq, nullptr, nullptr, nullptr);
    tc_gemm<1><<<gproj, blk, TCG_SMEM_BYTES>>>(Xcat, Wkcat, SEQ, MID, K3P,
        nullptr, Kcat, MID, bk, nullptr, nullptr, nullptr);
    tc_gemm<2><<<gproj, blk, TCG_SMEM_BYTES>>>(Xcat, Wvcat, SEQ, MID, K3P,
        V, nullptr, 0, bv, nullptr, nullptr, nullptr);

    // 3) V -> VtCat (transpose + split, B-side)
    {
        dim3 g(MID / 32, SEQ / 32), b(32, 8);
        transpose_split_v<<<g, b>>>(V, VtCat);
    }

    // 4) inverse row norms from cat (hi+lo)
    rownorm_cat<<<SEQ, 256>>>(Qcat, MID, 0, 1, invq);   // A-side: lo at block 1
    rownorm_cat<<<SEQ, 256>>>(Kcat, MID, 0, 2, invk);   // B-side: lo at block 2

    // 5) P = exp(QK^T * invq x invk) -> Pcat (A-side)  (scores in [-1,1]: no max)
    dim3 gsc(SEQ / BN, SEQ / BM);
    tc_gemm<3><<<gsc, blk, TCG_SMEM_BYTES>>>(Qcat, Kcat, SEQ, SEQ, K3P,
        nullptr, Pcat, SEQ, nullptr, invq, invk, nullptr);

    // 6) softmax denominators
    rowsum_cat<<<SEQ, 256>>>(Pcat, rowsum);

    // 7) out = (P @ V) / rowsum
    dim3 gout(MID / BN, SEQ / BM);
    tc_gemm<4><<<gout, blk, TCG_SMEM_BYTES>>>(Pcat, VtCat, SEQ, MID, K3PV,
        out, nullptr, 0, nullptr, nullptr, nullptr, rowsum);
}

// round 17
// speedup vs baseline: 3.5413x; 1.5815x over previous
#include <cuda_runtime.h>
#include <cuda_fp16.h>
#include <math.h>
#include <stdint.h>

#define SEQ 8192
#define EMB 1024
#define MID 1024

#define BM 128
#define BN 128
#define SROW  72
#define SROWB 144
#define TILE_BYTES (128 * SROWB)
#define TCG_SMEM_BYTES (4 * TILE_BYTES)

// ---------------- device scratch ----------------
__device__ __half g_Xcat2[(size_t)SEQ * 2 * EMB];   // [Xhi|Xlo]
__device__ __half g_Wq1 [(size_t)MID * EMB];        // Whi
__device__ __half g_Wk1 [(size_t)MID * EMB];
__device__ __half g_Wv1 [(size_t)MID * EMB];
__device__ __half g_Qcat2[(size_t)SEQ * 2 * MID];   // [Qhi|Qlo]
__device__ __half g_K1  [(size_t)SEQ * MID];        // Khi
__device__ float  g_V   [(size_t)SEQ * MID];
__device__ __half g_Vt2 [(size_t)MID * 2 * SEQ];    // [Vhi|Vlo] transposed
__device__ __half g_P1  [(size_t)SEQ * SEQ];        // 128 MB
__device__ float g_invq[SEQ];
__device__ float g_invk[SEQ];
__device__ float g_rowsum[SEQ];

// ---------------- PTX helpers ----------------
__device__ __forceinline__ uint32_t smem_u32(const void* p) {
    uint32_t a;
    asm("{ .reg .u64 t; cvta.to.shared.u64 t, %1; cvt.u32.u64 %0, t; }" : "=r"(a) : "l"(p));
    return a;
}
__device__ __forceinline__ void cp16(uint32_t saddr, const void* g) {
    asm volatile("cp.async.cg.shared.global [%0], [%1], 16;" :: "r"(saddr), "l"(g));
}
__device__ __forceinline__ void ldsm_x4(uint32_t* r, uint32_t addr) {
    asm volatile("ldmatrix.sync.aligned.m8n8.x4.shared.b16 {%0,%1,%2,%3}, [%4];"
                 : "=r"(r[0]), "=r"(r[1]), "=r"(r[2]), "=r"(r[3]) : "r"(addr));
}
__device__ __forceinline__ void mma16816(float* c, const uint32_t* a, uint32_t b0, uint32_t b1) {
    asm volatile(
        "mma.sync.aligned.m16n8k16.row.col.f32.f16.f16.f32 "
        "{%0,%1,%2,%3}, {%4,%5,%6,%7}, {%8,%9}, {%0,%1,%2,%3};"
        : "+f"(c[0]), "+f"(c[1]), "+f"(c[2]), "+f"(c[3])
        : "r"(a[0]), "r"(a[1]), "r"(a[2]), "r"(a[3]), "r"(b0), "r"(b1));
}

__device__ __forceinline__ void issue_chunk(const __half* Ap, const __half* Bp,
                                            uint32_t abuf, uint32_t bbuf,
                                            int strideA, int strideB, int tid)
{
#pragma unroll
    for (int i = 0; i < 4; i++) {
        int idx = tid + i * 256;
        int row = idx >> 3, v = idx & 7;
        cp16(abuf + row * SROWB + v * 16, Ap + (size_t)row * strideA + v * 8);
        cp16(bbuf + row * SROWB + v * 16, Bp + (size_t)row * strideB + v * 8);
    }
    asm volatile("cp.async.commit_group;" ::: "memory");
}

// ---------------- warp-MMA NT GEMM (fp16, wrap-addressed K) ----------------
// C[M,N] = A[M,K3-logical] * B[N,K3-logical]^T; physical cols KAW/KBW, wrapped.
// EPI 0: y=acc+bias[n] -> [hi|lo] fp16 (Q)
// EPI 1: y=acc+bias[n] -> single fp16 (K)
// EPI 2: y=acc+bias[n] -> fp32 (V)
// EPI 3: y=expf(acc*invm[m]*invn[n]) -> single fp16 (P)
// EPI 4: y=acc/rowsum[m] -> fp32 (out)
template <int EPI>
__global__ __launch_bounds__(256)
void tc_gemm(const __half* __restrict__ A, const __half* __restrict__ B,
             int M, int N, int K3, int KAW, int KBW,
             float* __restrict__ outf, __half* __restrict__ outh, int ncat,
             const float* __restrict__ bias, const float* __restrict__ invm,
             const float* __restrict__ invn, const float* __restrict__ rowsum)
{
    extern __shared__ char smem[];
    const uint32_t sbase = smem_u32(smem);
    const int tid  = threadIdx.x;
    const int lane = tid & 31, wid = tid >> 5;
    const int wm = wid & 3;
    const int wn = wid >> 2;
    const int m0 = blockIdx.y * BM;
    const int n0 = blockIdx.x * BN;
    const int kaMask = KAW - 1, kbMask = KBW - 1;

    float acc[2][8][4];
#pragma unroll
    for (int i = 0; i < 2; i++)
#pragma unroll
        for (int j = 0; j < 8; j++)
#pragma unroll
            for (int q = 0; q < 4; q++) acc[i][j][q] = 0.f;

    const int NCH = K3 >> 6;

    issue_chunk(A + (size_t)m0 * KAW, B + (size_t)n0 * KBW,
                sbase, sbase + TILE_BYTES, KAW, KBW, tid);

    for (int t = 0; t < NCH; t++) {
        if (t + 1 < NCH) {
            int b = (t + 1) & 1;
            int ca = ((t + 1) * 64) & kaMask;
            int cb = ((t + 1) * 64) & kbMask;
            issue_chunk(A + (size_t)m0 * KAW + ca,
                        B + (size_t)n0 * KBW + cb,
                        sbase + (b * 2) * TILE_BYTES,
                        sbase + (b * 2 + 1) * TILE_BYTES, KAW, KBW, tid);
            asm volatile("cp.async.wait_group 1;" ::: "memory");
        } else {
            asm volatile("cp.async.wait_group 0;" ::: "memory");
        }
        __syncthreads();

        const uint32_t abuf = sbase + ((t & 1) * 2) * TILE_BYTES;
        const uint32_t bbuf = abuf + TILE_BYTES;
        const uint32_t lrow = (lane & 15);
        const uint32_t lhalf = (lane >> 4) * 16;

#pragma unroll
        for (int kk = 0; kk < 4; kk++) {
            uint32_t af[2][4];
#pragma unroll
            for (int tm = 0; tm < 2; tm++)
                ldsm_x4(af[tm], abuf + (wm * 32 + tm * 16 + lrow) * SROWB + kk * 32 + lhalf);
            uint32_t bf[4][4];
#pragma unroll
            for (int g = 0; g < 4; g++)
                ldsm_x4(bf[g], bbuf + (wn * 64 + g * 16 + lrow) * SROWB + kk * 32 + lhalf);
#pragma unroll
            for (int tm = 0; tm < 2; tm++)
#pragma unroll
                for (int g = 0; g < 4; g++) {
                    mma16816(acc[tm][2 * g + 0], af[tm], bf[g][0], bf[g][2]);
                    mma16816(acc[tm][2 * g + 1], af[tm], bf[g][1], bf[g][3]);
                }
        }
        __syncthreads();
    }

    // ---------------- epilogue ----------------
    const int r_base = m0 + wm * 32;
    const int c_base = n0 + wn * 64;
#pragma unroll
    for (int tm = 0; tm < 2; tm++) {
        const int r0 = r_base + tm * 16 + (lane >> 2);
        const int r1 = r0 + 8;
        float sm0 = 0.f, sm1 = 0.f;
        if (EPI == 3) { sm0 = invm[r0]; sm1 = invm[r1]; }
        if (EPI == 4) { sm0 = 1.0f / rowsum[r0]; sm1 = 1.0f / rowsum[r1]; }
#pragma unroll
        for (int tn = 0; tn < 8; tn++) {
            const int c = c_base + tn * 8 + (lane & 3) * 2;
            float y00 = acc[tm][tn][0], y01 = acc[tm][tn][1];
            float y10 = acc[tm][tn][2], y11 = acc[tm][tn][3];
            if (EPI == 0 || EPI == 1 || EPI == 2) {
                float b0 = bias[c], b1 = bias[c + 1];
                y00 += b0; y01 += b1; y10 += b0; y11 += b1;
            }
            if (EPI == 3) {
                float i0 = invn[c], i1 = invn[c + 1];
                y00 = __expf(y00 * sm0 * i0); y01 = __expf(y01 * sm0 * i1);
                y10 = __expf(y10 * sm1 * i0); y11 = __expf(y11 * sm1 * i1);
            }
            if (EPI == 4) { y00 *= sm0; y01 *= sm0; y10 *= sm1; y11 *= sm1; }

            if (EPI == 2 || EPI == 4) {
                *(float2*)(outf + (size_t)r0 * N + c) = make_float2(y00, y01);
                *(float2*)(outf + (size_t)r1 * N + c) = make_float2(y10, y11);
            } else if (EPI == 0) {
                // [hi|lo] 2-block
#pragma unroll
                for (int rr = 0; rr < 2; rr++) {
                    int row = rr ? r1 : r0;
                    float a0 = rr ? y10 : y00, a1 = rr ? y11 : y01;
                    __half h0 = __float2half(a0), h1 = __float2half(a1);
                    __half l0 = __float2half(a0 - __half2float(h0));
                    __half l1 = __float2half(a1 - __half2float(h1));
                    __half2 hv; hv.x = h0; hv.y = h1;
                    __half2 lv; lv.x = l0; lv.y = l1;
                    __half* base = outh + (size_t)row * (2 * (size_t)ncat) + c;
                    *(__half2*)(base) = hv;
                    *(__half2*)(base + ncat) = lv;
                }
            } else {  // EPI 1 or 3: single fp16
#pragma unroll
                for (int rr = 0; rr < 2; rr++) {
                    int row = rr ? r1 : r0;
                    float a0 = rr ? y10 : y00, a1 = rr ? y11 : y01;
                    __half2 hv; hv.x = __float2half(a0); hv.y = __float2half(a1);
                    *(__half2*)(outh + (size_t)row * ncat + c) = hv;
                }
            }
        }
    }
}

// ---------------- pack fp32 -> fp16 [hi|lo] (A-side) ----------------
__global__ void pack2(const float* __restrict__ in, __half* __restrict__ out, int R, int C)
{
    int c4n = C >> 2;
    int i = blockIdx.x * 256 + threadIdx.x;
    if (i >= R * c4n) return;
    int r = i / c4n;
    int c = (i - r * c4n) * 4;
    float4 v = *(const float4*)(in + (size_t)r * C + c);
    __half h[4] = {__float2half(v.x), __float2half(v.y), __float2half(v.z), __float2half(v.w)};
    __half l[4] = {__float2half(v.x - __half2float(h[0])), __float2half(v.y - __half2float(h[1])),
                   __float2half(v.z - __half2float(h[2])), __float2half(v.w - __half2float(h[3]))};
    __half* b = out + (size_t)r * 2 * C + c;
    *(__half2*)(b)     = *(__half2*)&h[0]; *(__half2*)(b + 2)     = *(__half2*)&h[2];
    *(__half2*)(b + C) = *(__half2*)&l[0]; *(__half2*)(b + C + 2) = *(__half2*)&l[2];
}

// ---------------- pack fp32 -> fp16 hi only ----------------
__global__ void pack1(const float* __restrict__ in, __half* __restrict__ out, int R, int C)
{
    int c4n = C >> 2;
    int i = blockIdx.x * 256 + threadIdx.x;
    if (i >= R * c4n) return;
    int r = i / c4n;
    int c = (i - r * c4n) * 4;
    float4 v = *(const float4*)(in + (size_t)r * C + c);
    __half h[4] = {__float2half(v.x), __float2half(v.y), __float2half(v.z), __float2half(v.w)};
    __half* b = out + (size_t)r * C + c;
    *(__half2*)(b) = *(__half2*)&h[0]; *(__half2*)(b + 2) = *(__half2*)&h[2];
}

// ---------------- V [SEQ x MID] fp32 -> Vt2 [MID x 2*SEQ] fp16 [hi|lo] ----------------
__global__ void transpose_split_v(const float* __restrict__ V, __half* __restrict__ Vt2)
{
    __shared__ float tile[32][33];
    const int n0 = blockIdx.x * 32;
    const int s0 = blockIdx.y * 32;
    for (int i = threadIdx.y; i < 32; i += 8)
        tile[i][threadIdx.x] = V[(size_t)(s0 + i) * MID + n0 + threadIdx.x];
    __syncthreads();
    for (int i = threadIdx.y; i < 32; i += 8) {
        int n = n0 + i;
        int sv = s0 + threadIdx.x;
        float y = tile[threadIdx.x][i];
        __half h = __float2half(y);
        __half l = __float2half(y - __half2float(h));
        __half* b = Vt2 + (size_t)n * (2 * SEQ);
        b[sv] = h; b[SEQ + sv] = l;
    }
}

// ---------------- rownorm from [hi|lo] fp16 ----------------
__global__ void rownorm2(const __half* __restrict__ cat, int C, float* __restrict__ out)
{
    int row = blockIdx.x;
    const __half* h = cat + (size_t)row * 2 * C;
    const __half* l = h + C;
    float ssum = 0.f;
    for (int c = threadIdx.x; c < C; c += blockDim.x) {
        float y = __half2float(h[c]) + __half2float(l[c]);
        ssum += y * y;
    }
    __shared__ float red[256];
    red[threadIdx.x] = ssum;
    __syncthreads();
    for (int off = 128; off > 0; off >>= 1) {
        if (threadIdx.x < off) red[threadIdx.x] += red[threadIdx.x + off];
        __syncthreads();
    }
    if (threadIdx.x == 0) out[row] = rsqrtf(red[0]);
}

// ---------------- rownorm from single fp16 ----------------
__global__ void rownorm1(const __half* __restrict__ X, int C, float* __restrict__ out)
{
    int row = blockIdx.x;
    const __half* h = X + (size_t)row * C;
    float ssum = 0.f;
    for (int c = threadIdx.x; c < C; c += blockDim.x) {
        float y = __half2float(h[c]);
        ssum += y * y;
    }
    __shared__ float red[256];
    red[threadIdx.x] = ssum;
    __syncthreads();
    for (int off = 128; off > 0; off >>= 1) {
        if (threadIdx.x < off) red[threadIdx.x] += red[threadIdx.x + off];
        __syncthreads();
    }
    if (threadIdx.x == 0) out[row] = rsqrtf(red[0]);
}

// ---------------- rowsum over single-fp16 P ----------------
__global__ void rowsum1(const __half* __restrict__ P, float* __restrict__ out)
{
    int row = blockIdx.x;
    const __half* h = P + (size_t)row * SEQ;
    float ssum = 0.f;
    for (int c = threadIdx.x; c < SEQ; c += blockDim.x)
        ssum += __half2float(h[c]);
    __shared__ float red[256];
    red[threadIdx.x] = ssum;
    __syncthreads();
    for (int off = 128; off > 0; off >>= 1) {
        if (threadIdx.x < off) red[threadIdx.x] += red[threadIdx.x + off];
        __syncthreads();
    }
    if (threadIdx.x == 0) out[row] = red[0];
}

// ---------------- host ----------------
extern "C" void kernel_launch(void* const* d_in, const int* in_sizes, int n_in,
                              void* d_out, int out_size)
{
    const float* X  = (const float*)d_in[0];
    const float* Wq = (const float*)d_in[1];
    const float* bq = (const float*)d_in[2];
    const float* Wk = (const float*)d_in[3];
    const float* bk = (const float*)d_in[4];
    const float* Wv = (const float*)d_in[5];
    const float* bv = (const float*)d_in[6];
    float* out = (float*)d_out;

    __half *Xcat2, *Wq1, *Wk1, *Wv1, *Qcat2, *K1, *Vt2, *P1;
    float *V, *invq, *invk, *rowsum;
    cudaGetSymbolAddress((void**)&Xcat2, g_Xcat2);
    cudaGetSymbolAddress((void**)&Wq1,   g_Wq1);
    cudaGetSymbolAddress((void**)&Wk1,   g_Wk1);
    cudaGetSymbolAddress((void**)&Wv1,   g_Wv1);
    cudaGetSymbolAddress((void**)&Qcat2, g_Qcat2);
    cudaGetSymbolAddress((void**)&K1,    g_K1);
    cudaGetSymbolAddress((void**)&V,     g_V);
    cudaGetSymbolAddress((void**)&Vt2,   g_Vt2);
    cudaGetSymbolAddress((void**)&P1,    g_P1);
    cudaGetSymbolAddress((void**)&invq,  g_invq);
    cudaGetSymbolAddress((void**)&invk,  g_invk);
    cudaGetSymbolAddress((void**)&rowsum, g_rowsum);

    cudaFuncSetAttribute(tc_gemm<0>, cudaFuncAttributeMaxDynamicSharedMemorySize, TCG_SMEM_BYTES);
    cudaFuncSetAttribute(tc_gemm<1>, cudaFuncAttributeMaxDynamicSharedMemorySize, TCG_SMEM_BYTES);
    cudaFuncSetAttribute(tc_gemm<2>, cudaFuncAttributeMaxDynamicSharedMemorySize, TCG_SMEM_BYTES);
    cudaFuncSetAttribute(tc_gemm<3>, cudaFuncAttributeMaxDynamicSharedMemorySize, TCG_SMEM_BYTES);
    cudaFuncSetAttribute(tc_gemm<4>, cudaFuncAttributeMaxDynamicSharedMemorySize, TCG_SMEM_BYTES);

    // 1) pack: X -> [hi|lo]; W -> hi only
    pack2<<<(SEQ * (EMB / 4) + 255) / 256, 256>>>(X, Xcat2, SEQ, EMB);
    int wblk = (MID * (EMB / 4) + 255) / 256;
    pack1<<<wblk, 256>>>(Wq, Wq1, MID, EMB);
    pack1<<<wblk, 256>>>(Wk, Wk1, MID, EMB);
    pack1<<<wblk, 256>>>(Wv, Wv1, MID, EMB);

    dim3 blk(256);
    // 2) projections: K3=2048, A=Xcat2 (KAW=2048), B=W (KBW=1024, wraps)
    dim3 gproj(MID / BN, SEQ / BM);
    tc_gemm<0><<<gproj, blk, TCG_SMEM_BYTES>>>(Xcat2, Wq1, SEQ, MID, 2048, 2048, 1024,
        nullptr, Qcat2, MID, bq, nullptr, nullptr, nullptr);
    tc_gemm<1><<<gproj, blk, TCG_SMEM_BYTES>>>(Xcat2, Wk1, SEQ, MID, 2048, 2048, 1024,
        nullptr, K1, MID, bk, nullptr, nullptr, nullptr);
    tc_gemm<2><<<gproj, blk, TCG_SMEM_BYTES>>>(Xcat2, Wv1, SEQ, MID, 2048, 2048, 1024,
        V, nullptr, 0, bv, nullptr, nullptr, nullptr);

    // 3) V -> Vt2 [hi|lo]
    {
        dim3 g(MID / 32, SEQ / 32), b(32, 8);
        transpose_split_v<<<g, b>>>(V, Vt2);
    }

    // 4) row norms
    rownorm2<<<SEQ, 256>>>(Qcat2, MID, invq);
    rownorm1<<<SEQ, 256>>>(K1, MID, invk);

    // 5) P = exp(QK^T * invq x invk): K3=2048, A=Qcat2(2048), B=K1(1024, wraps)
    dim3 gsc(SEQ / BN, SEQ / BM);
    tc_gemm<3><<<gsc, blk, TCG_SMEM_BYTES>>>(Qcat2, K1, SEQ, SEQ, 2048, 2048, 1024,
        nullptr, P1, SEQ, nullptr, invq, invk, nullptr);

    // 6) rowsum
    rowsum1<<<SEQ, 256>>>(P1, rowsum);

    // 7) out = (P @ V)/rowsum: K3=16384, A=P1(8192, wraps), B=Vt2(16384)
    dim3 gout(MID / BN, SEQ / BM);
    tc_gemm<4><<<gout, blk, TCG_SMEM_BYTES>>>(P1, Vt2, SEQ, MID, 16384, 8192, 16384,
        out, nullptr, 0, nullptr, nullptr, nullptr, rowsum);
}